// round 11
// baseline (speedup 1.0000x reference)
#include <cuda_runtime.h>
#include <cuda_bf16.h>

#define BB 2
#define TT 16
#define DD 64
#define HW 4096
#define NELEM 8388608   // B*T*D*H*W

// ---------------- scratch (device globals; no allocation allowed) -------------
__device__ float g_xnr[NELEM], g_xni[NELEM];   // spatially-normed x
__device__ float g_cr [NELEM], g_ci [NELEM];   // clifford conv out
__device__ float g_x1r[NELEM], g_x1i[NELEM];   // after spatial stage
__device__ float g_tnr[NELEM], g_tni[NELEM];   // temporally-normed
__device__ float g_er [NELEM], g_ei [NELEM];   // x_eig, scanned in place
__device__ float g_x2r[NELEM], g_x2i[NELEM];   // after temporal stage
__device__ float2 g_evo[BB*TT*DD];

// ---------------- complex layernorm over 128 feats per (bt,hw) ---------------
__global__ void cnorm_kernel(const float* __restrict__ inr, const float* __restrict__ ini,
                             const float* __restrict__ w,   const float* __restrict__ b,
                             float* __restrict__ outr, float* __restrict__ outi)
{
    int p = blockIdx.x * blockDim.x + threadIdx.x;     // 0..131071
    int base = (p >> 12) * (DD * HW) + (p & 4095);
    float sum = 0.f, sq = 0.f;
#pragma unroll 8
    for (int d = 0; d < DD; d++) {
        float a = inr[base + d * HW], c = ini[base + d * HW];
        sum += a + c; sq += a * a + c * c;
    }
    float mu = sum * (1.f / 128.f);
    float rs = rsqrtf(sq * (1.f / 128.f) - mu * mu + 1e-5f);
#pragma unroll 8
    for (int d = 0; d < DD; d++) {
        float a = inr[base + d * HW], c = ini[base + d * HW];
        outr[base + d * HW] = (a - mu) * rs * w[d]      + b[d];
        outi[base + d * HW] = (c - mu) * rs * w[DD + d] + b[DD + d];
    }
}

// ---------------- Clifford complex 3x3 conv, 64->64 ch -----------------------
__global__ void conv_kernel(const float* __restrict__ xr, const float* __restrict__ xi,
                            const float* __restrict__ wr, const float* __restrict__ wi,
                            const float* __restrict__ br, const float* __restrict__ bi,
                            float* __restrict__ outr, float* __restrict__ outi)
{
    __shared__ float2 s_in[18][19];
    __shared__ float2 s_w[16][9];
    int h0 = (blockIdx.x >> 2) * 16, w0 = (blockIdx.x & 3) * 16;
    int oc0 = blockIdx.y * 16;
    int bt = blockIdx.z;
    int tx = threadIdx.x, ty = threadIdx.y, tid = ty * 16 + tx;
    float accr[16], acci[16];
#pragma unroll
    for (int o = 0; o < 16; o++) { accr[o] = 0.f; acci[o] = 0.f; }
    for (int ic = 0; ic < 64; ic++) {
        const float* pr = xr + (bt * 64 + ic) * HW;
        const float* pi = xi + (bt * 64 + ic) * HW;
        for (int idx = tid; idx < 324; idx += 256) {
            int r = idx / 18, c = idx - r * 18;
            int gh = h0 - 1 + r, gw = w0 - 1 + c;
            float vr = 0.f, vi = 0.f;
            if ((unsigned)gh < 64u && (unsigned)gw < 64u) { vr = pr[gh*64+gw]; vi = pi[gh*64+gw]; }
            s_in[r][c] = make_float2(vr, vi);
        }
        if (tid < 144) {
            int o = tid / 9, k = tid - o * 9;
            int widx = ((oc0 + o) * 64 + ic) * 9 + k;
            s_w[o][k] = make_float2(wr[widx], wi[widx]);
        }
        __syncthreads();
#pragma unroll
        for (int ky = 0; ky < 3; ky++)
#pragma unroll
        for (int kx = 0; kx < 3; kx++) {
            float2 a = s_in[ty + ky][tx + kx];
#pragma unroll
            for (int o = 0; o < 16; o++) {
                float2 wv = s_w[o][ky * 3 + kx];
                accr[o] += a.x * wv.x - a.y * wv.y;
                acci[o] += a.x * wv.y + a.y * wv.x;
            }
        }
        __syncthreads();
    }
    int opos = (h0 + ty) * 64 + (w0 + tx);
#pragma unroll
    for (int o = 0; o < 16; o++) {
        int gi = (bt * 64 + oc0 + o) * HW + opos;
        outr[gi] = accr[o] + br[oc0 + o];
        outi[gi] = acci[o] + bi[oc0 + o];
    }
}

// ---------------- 64-pt DFT pass (AXIS 0: along W rows; 1: along H cols) -----
template<int AXIS>
__device__ __forceinline__ void dft_pass(float2* sA, const float2* stw, int tid,
                                         int inverse, float scale)
{
    int a = tid >> 2;
    int jb = (tid & 3) * 16;
    float2 acc[16];
#pragma unroll
    for (int j = 0; j < 16; j++) acc[j] = make_float2(0.f, 0.f);
    for (int k = 0; k < 64; k++) {
        float2 v = (AXIS == 0) ? sA[a * 65 + k] : sA[k * 65 + a];
#pragma unroll
        for (int j = 0; j < 16; j++) {
            int jj = inverse ? ((64 - (jb + j)) & 63) : (jb + j);
            float2 w = stw[(jj * k) & 63];
            acc[j].x += v.x * w.x - v.y * w.y;
            acc[j].y += v.x * w.y + v.y * w.x;
        }
    }
    __syncthreads();
#pragma unroll
    for (int j = 0; j < 16; j++) {
        float2 r = make_float2(acc[j].x * scale, acc[j].y * scale);
        if (AXIS == 0) sA[a * 65 + jb + j] = r;
        else           sA[(jb + j) * 65 + a] = r;
    }
    __syncthreads();
}

// spectral mix fused with gated combine + residual; block per (bt,d)
__global__ void spec_kernel(const float* __restrict__ xnr, const float* __restrict__ xni,
                            const float* __restrict__ swr, const float* __restrict__ swi,
                            const float* __restrict__ clr, const float* __restrict__ cli,
                            const float* __restrict__ x0r, const float* __restrict__ x0i,
                            const float* __restrict__ gate,
                            float* __restrict__ outr, float* __restrict__ outi)
{
    __shared__ float2 sA[64 * 65];
    __shared__ float2 stw[64];
    int tid = threadIdx.x;
    int bd = blockIdx.x;
    int d = bd & 63;
    int base = bd * HW;
    if (tid < 64) {
        float s, c;
        sincospif((float)tid * (1.f / 32.f), &s, &c);
        stw[tid] = make_float2(c, -s);
    }
    for (int i = tid; i < 4096; i += 256)
        sA[(i >> 6) * 65 + (i & 63)] = make_float2(xnr[base + i], xni[base + i]);
    __syncthreads();
    dft_pass<0>(sA, stw, tid, 0, 1.f);
    dft_pass<1>(sA, stw, tid, 0, 1.f);
    for (int i = tid; i < 4096; i += 256) {
        float2 v = sA[(i >> 6) * 65 + (i & 63)];
        float wrv = swr[d * HW + i], wiv = swi[d * HW + i];
        sA[(i >> 6) * 65 + (i & 63)] = make_float2(v.x * wrv - v.y * wiv, v.x * wiv + v.y * wrv);
    }
    __syncthreads();
    dft_pass<1>(sA, stw, tid, 1, 1.f / 64.f);
    dft_pass<0>(sA, stw, tid, 1, 1.f / 64.f);
    float g = gate[0], og = 1.f - g;
    for (int i = tid; i < 4096; i += 256) {
        float2 s = sA[(i >> 6) * 65 + (i & 63)];
        int gi = base + i;
        outr[gi] = g * clr[gi] + og * s.x + x0r[gi];
        outi[gi] = g * cli[gi] + og * s.y + x0i[gi];
    }
}

// ---------------- complex projection y[d] = sum_k x[k]*M[d,k] (+resid) -------
__global__ void cproj_kernel(const float* __restrict__ xr, const float* __restrict__ xi,
                             const float* __restrict__ Mre, const float* __restrict__ Mim,
                             const float* __restrict__ resr, const float* __restrict__ resi,
                             float* __restrict__ outr, float* __restrict__ outi,
                             int add_resid)
{
    __shared__ float2 sM[16 * 64];
    int tid = threadIdx.x;
    int oc0 = blockIdx.y * 16;
    for (int i = tid; i < 1024; i += 256) {
        int o = i >> 6, k = i & 63;
        sM[i] = make_float2(Mre[(oc0 + o) * 64 + k], Mim[(oc0 + o) * 64 + k]);
    }
    __syncthreads();
    int p = blockIdx.x * 256 + tid;
    int base = (p >> 12) * (DD * HW) + (p & 4095);
    float accr[16], acci[16];
#pragma unroll
    for (int o = 0; o < 16; o++) { accr[o] = 0.f; acci[o] = 0.f; }
    for (int k = 0; k < 64; k++) {
        float a = xr[base + k * HW], c = xi[base + k * HW];
#pragma unroll
        for (int o = 0; o < 16; o++) {
            float2 m = sM[o * 64 + k];
            accr[o] += a * m.x - c * m.y;
            acci[o] += a * m.y + c * m.x;
        }
    }
#pragma unroll
    for (int o = 0; o < 16; o++) {
        int gi = base + (oc0 + o) * HW;
        float vr = accr[o], vi = acci[o];
        if (add_resid) { vr += resr[gi]; vi += resi[gi]; }
        outr[gi] = vr; outi[gi] = vi;
    }
}

// ---------------- evo = exp(lam * dt), lam = (-softplus(re), im) -------------
__global__ void evo_kernel(const float* __restrict__ dt,
                           const float* __restrict__ lam_re, const float* __restrict__ lam_im,
                           float2* __restrict__ evo)
{
    int i = blockIdx.x * blockDim.x + threadIdx.x;
    if (i >= BB * TT * DD) return;
    int d = i & 63;
    int b = i >> 10, t = (i >> 6) & 15;
    float dtv = dt[b * 16 + t];
    float lre = -log1pf(expf(lam_re[d]));
    float m = expf(lre * dtv);
    float s, c;
    sincosf(lam_im[d] * dtv, &s, &c);
    evo[i] = make_float2(m * c, m * s);
}

// ---------------- diagonal temporal scan over T=16, in place -----------------
__global__ void scan_kernel(float* __restrict__ er, float* __restrict__ ei,
                            const float2* __restrict__ evo)
{
    int idx = blockIdx.x * 256 + threadIdx.x;   // B*D*HW = 524288
    int b = idx >> 18;
    int dhw = idx & 262143;
    int d = dhw >> 12;
    float hr = 0.f, hi = 0.f;
#pragma unroll
    for (int t = 0; t < 16; t++) {
        float2 a = evo[(b * 16 + t) * 64 + d];
        int gi = (b * 16 + t) * (DD * HW) + dhw;
        float xr = er[gi], xv = ei[gi];
        float nr = a.x * hr - a.y * hi + xr;
        float ni = a.x * hi + a.y * hr + xv;
        hr = nr; hi = ni;
        er[gi] = hr; ei[gi] = hi;
    }
}

// ---------------- fused LN + MLP(128->256 gelu ->128) + resid -> output ------
__global__ void mlp_kernel(const float* __restrict__ x2r, const float* __restrict__ x2i,
                           const float* __restrict__ lnw, const float* __restrict__ lnb,
                           const float* __restrict__ w1,  const float* __restrict__ b1,
                           const float* __restrict__ w2,  const float* __restrict__ b2,
                           float* __restrict__ out)
{
    __shared__ __align__(16) float smem[12288];  // 48 KB
    float* sZ = smem;            // [128 feat][32 pos]
    float* sH = smem + 4096;     // [32 pos][256 hid]
    int tid = threadIdx.x;
    int p0 = blockIdx.x * 32;
    int base = (p0 >> 12) * (DD * HW) + (p0 & 4095);

    for (int i = tid; i < 2048; i += 256) {
        int d = i >> 5, p = i & 31;
        sZ[d * 32 + p]        = x2r[base + d * HW + p];
        sZ[(64 + d) * 32 + p] = x2i[base + d * HW + p];
    }
    __syncthreads();
    {   // LN: 8 threads per position
        int p = tid >> 3, l = tid & 7;
        float sum = 0.f, sq = 0.f;
#pragma unroll
        for (int c = l; c < 128; c += 8) { float v = sZ[c * 32 + p]; sum += v; sq += v * v; }
#pragma unroll
        for (int m = 1; m < 8; m <<= 1) {
            sum += __shfl_xor_sync(0xffffffffu, sum, m);
            sq  += __shfl_xor_sync(0xffffffffu, sq,  m);
        }
        float mu = sum * (1.f / 128.f);
        float rs = rsqrtf(sq * (1.f / 128.f) - mu * mu + 1e-5f);
#pragma unroll
        for (int c = l; c < 128; c += 8) {
            float v = sZ[c * 32 + p];
            sZ[c * 32 + p] = (v - mu) * rs * lnw[c] + lnb[c];
        }
    }
    __syncthreads();
    {   // GEMM1 + gelu: thread = hidden unit j
        float acc[32];
#pragma unroll
        for (int p = 0; p < 32; p++) acc[p] = 0.f;
        int j = tid;
        for (int k = 0; k < 128; k++) {
            float wv = w1[k * 256 + j];
            const float2* zp = (const float2*)&sZ[k * 32];
#pragma unroll
            for (int q = 0; q < 16; q++) {
                float2 z2 = zp[q];
                acc[2 * q]     += z2.x * wv;
                acc[2 * q + 1] += z2.y * wv;
            }
        }
        float bb = b1[j];
#pragma unroll
        for (int p = 0; p < 32; p++) {
            float h = acc[p] + bb;
            h = 0.5f * h * (1.f + erff(h * 0.70710678118654752f));
            sH[p * 256 + j] = h;
        }
    }
    __syncthreads();
    float acc2[16];
    int o = tid & 127, pb = (tid >> 7) * 16;
    {   // GEMM2: thread = (out unit, half the positions)
#pragma unroll
        for (int q = 0; q < 16; q++) acc2[q] = 0.f;
        for (int k = 0; k < 256; k += 2) {
            float wv0 = w2[k * 128 + o];
            float wv1 = w2[(k + 1) * 128 + o];
#pragma unroll
            for (int q = 0; q < 16; q++) {
                float2 h2 = *(const float2*)&sH[(pb + q) * 256 + k];
                acc2[q] += h2.x * wv0 + h2.y * wv1;
            }
        }
        float bb = b2[o];
#pragma unroll
        for (int q = 0; q < 16; q++) acc2[q] += bb;
    }
    __syncthreads();
#pragma unroll
    for (int q = 0; q < 16; q++) smem[(pb + q) * 130 + o] = acc2[q];
    __syncthreads();
    for (int i = tid; i < 4096; i += 256) {
        int c = i >> 5, p = i & 31;
        int dd = c >> 1, comp = c & 1;
        int gi = base + dd * HW + p;
        float v = smem[p * 130 + (comp ? 64 + dd : dd)];
        out[2 * gi + comp] = v + (comp ? x2i[gi] : x2r[gi]);
    }
}

// -----------------------------------------------------------------------------
extern "C" void kernel_launch(void* const* d_in, const int* in_sizes, int n_in,
                              void* d_out, int out_size)
{
    (void)in_sizes; (void)n_in; (void)out_size;
    const float* x_real  = (const float*)d_in[0];
    const float* x_imag  = (const float*)d_in[1];
    const float* dt      = (const float*)d_in[2];
    const float* ln_s_w  = (const float*)d_in[3];
    const float* ln_s_b  = (const float*)d_in[4];
    const float* ln_t_w  = (const float*)d_in[5];
    const float* ln_t_b  = (const float*)d_in[6];
    const float* ln_m_w  = (const float*)d_in[7];
    const float* ln_m_b  = (const float*)d_in[8];
    const float* cw_r    = (const float*)d_in[9];
    const float* cw_i    = (const float*)d_in[10];
    const float* cb_r    = (const float*)d_in[11];
    const float* cb_i    = (const float*)d_in[12];
    const float* spec_wr = (const float*)d_in[13];
    const float* spec_wi = (const float*)d_in[14];
    const float* gate    = (const float*)d_in[15];
    const float* lam_re  = (const float*)d_in[16];
    const float* lam_im  = (const float*)d_in[17];
    const float* V_re    = (const float*)d_in[18];
    const float* V_im    = (const float*)d_in[19];
    const float* Vinv_re = (const float*)d_in[20];
    const float* Vinv_im = (const float*)d_in[21];
    const float* w1      = (const float*)d_in[22];
    const float* b1      = (const float*)d_in[23];
    const float* w2      = (const float*)d_in[24];
    const float* b2      = (const float*)d_in[25];
    float* out = (float*)d_out;

    float *xnr, *xni, *cr, *ci, *x1r, *x1i, *tnr, *tni, *er, *ei, *x2r, *x2i;
    float2* evo;
    cudaGetSymbolAddress((void**)&xnr, g_xnr);
    cudaGetSymbolAddress((void**)&xni, g_xni);
    cudaGetSymbolAddress((void**)&cr,  g_cr);
    cudaGetSymbolAddress((void**)&ci,  g_ci);
    cudaGetSymbolAddress((void**)&x1r, g_x1r);
    cudaGetSymbolAddress((void**)&x1i, g_x1i);
    cudaGetSymbolAddress((void**)&tnr, g_tnr);
    cudaGetSymbolAddress((void**)&tni, g_tni);
    cudaGetSymbolAddress((void**)&er,  g_er);
    cudaGetSymbolAddress((void**)&ei,  g_ei);
    cudaGetSymbolAddress((void**)&x2r, g_x2r);
    cudaGetSymbolAddress((void**)&x2i, g_x2i);
    cudaGetSymbolAddress((void**)&evo, g_evo);

    // ---- spatial stage ----
    cnorm_kernel<<<512, 256>>>(x_real, x_imag, ln_s_w, ln_s_b, xnr, xni);
    conv_kernel<<<dim3(16, 4, 32), dim3(16, 16)>>>(xnr, xni, cw_r, cw_i, cb_r, cb_i, cr, ci);
    spec_kernel<<<2048, 256>>>(xnr, xni, spec_wr, spec_wi, cr, ci,
                               x_real, x_imag, gate, x1r, x1i);
    // ---- temporal stage ----
    cnorm_kernel<<<512, 256>>>(x1r, x1i, ln_t_w, ln_t_b, tnr, tni);
    cproj_kernel<<<dim3(512, 4), 256>>>(tnr, tni, Vinv_re, Vinv_im,
                                        tnr, tni, er, ei, 0);
    evo_kernel<<<8, 256>>>(dt, lam_re, lam_im, evo);
    scan_kernel<<<2048, 256>>>(er, ei, evo);
    cproj_kernel<<<dim3(512, 4), 256>>>(er, ei, V_re, V_im,
                                        x1r, x1i, x2r, x2i, 1);
    // ---- MLP stage -> final interleaved output ----
    mlp_kernel<<<4096, 256>>>(x2r, x2i, ln_m_w, ln_m_b, w1, b1, w2, b2, out);
}

// round 12
// speedup vs baseline: 1.1569x; 1.1569x over previous
#include <cuda_runtime.h>
#include <cuda_bf16.h>

#define BB 2
#define TT 16
#define DD 64
#define HW 4096
#define NELEM 8388608   // B*T*D*H*W

// ---------------- scratch (device globals; no allocation allowed) -------------
__device__ float g_xnr[NELEM], g_xni[NELEM];   // spatially-normed x
__device__ float g_cr [NELEM], g_ci [NELEM];   // clifford conv out
__device__ float g_x1r[NELEM], g_x1i[NELEM];   // after spatial stage
__device__ float g_tnr[NELEM], g_tni[NELEM];   // temporally-normed
__device__ float g_er [NELEM], g_ei [NELEM];   // x_eig, scanned in place
__device__ float g_x2r[NELEM], g_x2i[NELEM];   // after temporal stage
__device__ float2 g_evo[BB*TT*DD];

// ---------------- complex layernorm over 128 feats per (bt,hw) ---------------
__global__ void cnorm_kernel(const float* __restrict__ inr, const float* __restrict__ ini,
                             const float* __restrict__ w,   const float* __restrict__ b,
                             float* __restrict__ outr, float* __restrict__ outi)
{
    int p = blockIdx.x * blockDim.x + threadIdx.x;     // 0..131071
    int base = (p >> 12) * (DD * HW) + (p & 4095);
    float sum = 0.f, sq = 0.f;
#pragma unroll 8
    for (int d = 0; d < DD; d++) {
        float a = inr[base + d * HW], c = ini[base + d * HW];
        sum += a + c; sq += a * a + c * c;
    }
    float mu = sum * (1.f / 128.f);
    float rs = rsqrtf(sq * (1.f / 128.f) - mu * mu + 1e-5f);
#pragma unroll 8
    for (int d = 0; d < DD; d++) {
        float a = inr[base + d * HW], c = ini[base + d * HW];
        outr[base + d * HW] = (a - mu) * rs * w[d]      + b[d];
        outi[base + d * HW] = (c - mu) * rs * w[DD + d] + b[DD + d];
    }
}

// ---------------- Clifford complex 3x3 conv, 64->64 ch -----------------------
// tile = 16 rows x 64 cols; thread (tx,ty) owns row ty, cols 4tx..4tx+3, 8 oc.
// grid: (4 row-tiles, 8 oc-groups, 32 bt), block (16,16)
__global__ void __launch_bounds__(256) conv_kernel(
                            const float* __restrict__ xr, const float* __restrict__ xi,
                            const float* __restrict__ wr, const float* __restrict__ wi,
                            const float* __restrict__ br, const float* __restrict__ bi,
                            float* __restrict__ outr, float* __restrict__ outi)
{
    __shared__ float2 s_in[18 * 66];   // rows h0-1..h0+16, cols -1..64
    __shared__ float2 s_w[8 * 9];
    int h0  = blockIdx.x * 16;
    int oc0 = blockIdx.y * 8;
    int bt  = blockIdx.z;
    int tx = threadIdx.x, ty = threadIdx.y;
    int tid = ty * 16 + tx;

    float2 acc[8][4];
#pragma unroll
    for (int o = 0; o < 8; o++)
#pragma unroll
        for (int p = 0; p < 4; p++) acc[o][p] = make_float2(0.f, 0.f);

    for (int ic = 0; ic < 64; ic++) {
        const float* pr = xr + (bt * 64 + ic) * HW;
        const float* pi = xi + (bt * 64 + ic) * HW;
        for (int idx = tid; idx < 18 * 66; idx += 256) {
            int r = idx / 66, c = idx - r * 66;
            int gh = h0 - 1 + r, gw = c - 1;
            float vr = 0.f, vi = 0.f;
            if ((unsigned)gh < 64u && (unsigned)gw < 64u) {
                int g = gh * 64 + gw; vr = pr[g]; vi = pi[g];
            }
            s_in[idx] = make_float2(vr, vi);
        }
        if (tid < 72) {
            int o = tid / 9, k = tid - o * 9;
            int widx = ((oc0 + o) * 64 + ic) * 9 + k;
            s_w[tid] = make_float2(wr[widx], wi[widx]);
        }
        __syncthreads();
#pragma unroll
        for (int ky = 0; ky < 3; ky++) {
            const float4* rowp = (const float4*)&s_in[(ty + ky) * 66 + 4 * tx];
            float4 q0 = rowp[0], q1 = rowp[1], q2 = rowp[2];
            float2 arow[6];
            arow[0] = make_float2(q0.x, q0.y); arow[1] = make_float2(q0.z, q0.w);
            arow[2] = make_float2(q1.x, q1.y); arow[3] = make_float2(q1.z, q1.w);
            arow[4] = make_float2(q2.x, q2.y); arow[5] = make_float2(q2.z, q2.w);
#pragma unroll
            for (int kx = 0; kx < 3; kx++) {
#pragma unroll
                for (int o = 0; o < 8; o++) {
                    float2 wv = s_w[o * 9 + ky * 3 + kx];
#pragma unroll
                    for (int p = 0; p < 4; p++) {
                        float2 a = arow[p + kx];
                        acc[o][p].x += a.x * wv.x - a.y * wv.y;
                        acc[o][p].y += a.x * wv.y + a.y * wv.x;
                    }
                }
            }
        }
        __syncthreads();
    }
    int opos = (h0 + ty) * 64 + 4 * tx;
#pragma unroll
    for (int o = 0; o < 8; o++) {
        float bre = br[oc0 + o], bim = bi[oc0 + o];
        int gi = (bt * 64 + oc0 + o) * HW + opos;
        float4 vr4 = make_float4(acc[o][0].x + bre, acc[o][1].x + bre,
                                 acc[o][2].x + bre, acc[o][3].x + bre);
        float4 vi4 = make_float4(acc[o][0].y + bim, acc[o][1].y + bim,
                                 acc[o][2].y + bim, acc[o][3].y + bim);
        *(float4*)&outr[gi] = vr4;
        *(float4*)&outi[gi] = vi4;
    }
}

// ---------------- 64-pt DFT pass, warp-uniform twiddles ----------------------
// AXIS 0: transform along W (line = row a); AXIS 1: along H (line = col a).
// Each thread: one line, 32 consecutive outputs. INV => conj twiddle.
template<int AXIS, bool INV>
__device__ __forceinline__ void dft_pass(float* sRe, float* sIm, const float2* stw,
                                         int a, int jbase, float scale)
{
    float ar[32], ai[32];
#pragma unroll
    for (int j = 0; j < 32; j++) { ar[j] = 0.f; ai[j] = 0.f; }
    for (int k = 0; k < 64; k++) {
        float vr = (AXIS == 0) ? sRe[a * 65 + k] : sRe[k * 65 + a];
        float vi = (AXIS == 0) ? sIm[a * 65 + k] : sIm[k * 65 + a];
#pragma unroll
        for (int j = 0; j < 32; j++) {
            float2 w = stw[((jbase + j) * k) & 63];   // uniform across warp
            float wy = INV ? -w.y : w.y;
            ar[j] += vr * w.x - vi * wy;
            ai[j] += vr * wy + vi * w.x;
        }
    }
    __syncthreads();
#pragma unroll
    for (int j = 0; j < 32; j++) {
        int jj = jbase + j;
        if (AXIS == 0) { sRe[a * 65 + jj] = ar[j] * scale; sIm[a * 65 + jj] = ai[j] * scale; }
        else           { sRe[jj * 65 + a] = ar[j] * scale; sIm[jj * 65 + a] = ai[j] * scale; }
    }
    __syncthreads();
}

// spectral mix fused with gated combine + residual; block per (bt,d), 128 thr
__global__ void __launch_bounds__(128) spec_kernel(
                            const float* __restrict__ xnr, const float* __restrict__ xni,
                            const float* __restrict__ swr, const float* __restrict__ swi,
                            const float* __restrict__ clr, const float* __restrict__ cli,
                            const float* __restrict__ x0r, const float* __restrict__ x0i,
                            const float* __restrict__ gate,
                            float* __restrict__ outr, float* __restrict__ outi)
{
    __shared__ float sRe[64 * 65];
    __shared__ float sIm[64 * 65];
    __shared__ float2 stw[64];
    int tid = threadIdx.x;
    int warp = tid >> 5, lane = tid & 31;
    int a = lane + 32 * (warp >> 1);     // line index 0..63
    int jbase = (warp & 1) * 32;         // output half
    int bd = blockIdx.x;
    int d = bd & 63;
    int base = bd * HW;

    if (tid < 64) {
        float s, c;
        sincospif((float)tid * (1.f / 32.f), &s, &c);   // 2*pi*tid/64
        stw[tid] = make_float2(c, -s);
    }
    for (int i = tid; i < 4096; i += 128) {
        int r = i >> 6, c = i & 63;
        sRe[r * 65 + c] = xnr[base + i];
        sIm[r * 65 + c] = xni[base + i];
    }
    __syncthreads();

    dft_pass<0, false>(sRe, sIm, stw, a, jbase, 1.f);   // fft along W
    dft_pass<1, false>(sRe, sIm, stw, a, jbase, 1.f);   // fft along H

    for (int i = tid; i < 4096; i += 128) {
        int r = i >> 6, c = i & 63;
        float vr = sRe[r * 65 + c], vi = sIm[r * 65 + c];
        float wrv = swr[d * HW + i], wiv = swi[d * HW + i];
        sRe[r * 65 + c] = vr * wrv - vi * wiv;
        sIm[r * 65 + c] = vr * wiv + vi * wrv;
    }
    __syncthreads();

    dft_pass<1, true>(sRe, sIm, stw, a, jbase, 1.f / 64.f);  // ifft along H
    dft_pass<0, true>(sRe, sIm, stw, a, jbase, 1.f / 64.f);  // ifft along W

    float g = gate[0], og = 1.f - g;
    for (int i = tid; i < 4096; i += 128) {
        int r = i >> 6, c = i & 63;
        int gi = base + i;
        outr[gi] = g * clr[gi] + og * sRe[r * 65 + c] + x0r[gi];
        outi[gi] = g * cli[gi] + og * sIm[r * 65 + c] + x0i[gi];
    }
}

// ---------------- complex projection y[d] = sum_k x[k]*M[d,k] (+resid) -------
__global__ void cproj_kernel(const float* __restrict__ xr, const float* __restrict__ xi,
                             const float* __restrict__ Mre, const float* __restrict__ Mim,
                             const float* __restrict__ resr, const float* __restrict__ resi,
                             float* __restrict__ outr, float* __restrict__ outi,
                             int add_resid)
{
    __shared__ float2 sM[16 * 64];
    int tid = threadIdx.x;
    int oc0 = blockIdx.y * 16;
    for (int i = tid; i < 1024; i += 256) {
        int o = i >> 6, k = i & 63;
        sM[i] = make_float2(Mre[(oc0 + o) * 64 + k], Mim[(oc0 + o) * 64 + k]);
    }
    __syncthreads();
    int p = blockIdx.x * 256 + tid;
    int base = (p >> 12) * (DD * HW) + (p & 4095);
    float accr[16], acci[16];
#pragma unroll
    for (int o = 0; o < 16; o++) { accr[o] = 0.f; acci[o] = 0.f; }
    for (int k = 0; k < 64; k++) {
        float a = xr[base + k * HW], c = xi[base + k * HW];
#pragma unroll
        for (int o = 0; o < 16; o++) {
            float2 m = sM[o * 64 + k];
            accr[o] += a * m.x - c * m.y;
            acci[o] += a * m.y + c * m.x;
        }
    }
#pragma unroll
    for (int o = 0; o < 16; o++) {
        int gi = base + (oc0 + o) * HW;
        float vr = accr[o], vi = acci[o];
        if (add_resid) { vr += resr[gi]; vi += resi[gi]; }
        outr[gi] = vr; outi[gi] = vi;
    }
}

// ---------------- evo = exp(lam * dt), lam = (-softplus(re), im) -------------
__global__ void evo_kernel(const float* __restrict__ dt,
                           const float* __restrict__ lam_re, const float* __restrict__ lam_im,
                           float2* __restrict__ evo)
{
    int i = blockIdx.x * blockDim.x + threadIdx.x;
    if (i >= BB * TT * DD) return;
    int d = i & 63;
    int b = i >> 10, t = (i >> 6) & 15;
    float dtv = dt[b * 16 + t];
    float lre = -log1pf(expf(lam_re[d]));
    float m = expf(lre * dtv);
    float s, c;
    sincosf(lam_im[d] * dtv, &s, &c);
    evo[i] = make_float2(m * c, m * s);
}

// ---------------- diagonal temporal scan over T=16, in place -----------------
__global__ void scan_kernel(float* __restrict__ er, float* __restrict__ ei,
                            const float2* __restrict__ evo)
{
    int idx = blockIdx.x * 256 + threadIdx.x;   // B*D*HW = 524288
    int b = idx >> 18;
    int dhw = idx & 262143;
    int d = dhw >> 12;
    float hr = 0.f, hi = 0.f;
#pragma unroll
    for (int t = 0; t < 16; t++) {
        float2 a = evo[(b * 16 + t) * 64 + d];
        int gi = (b * 16 + t) * (DD * HW) + dhw;
        float xr = er[gi], xv = ei[gi];
        float nr = a.x * hr - a.y * hi + xr;
        float ni = a.x * hi + a.y * hr + xv;
        hr = nr; hi = ni;
        er[gi] = hr; ei[gi] = hi;
    }
}

// ---------------- fused LN + MLP(128->256 gelu ->128) + resid -> output ------
__global__ void mlp_kernel(const float* __restrict__ x2r, const float* __restrict__ x2i,
                           const float* __restrict__ lnw, const float* __restrict__ lnb,
                           const float* __restrict__ w1,  const float* __restrict__ b1,
                           const float* __restrict__ w2,  const float* __restrict__ b2,
                           float* __restrict__ out)
{
    __shared__ __align__(16) float smem[12288];  // 48 KB
    float* sZ = smem;            // [128 feat][32 pos]
    float* sH = smem + 4096;     // [32 pos][256 hid]
    int tid = threadIdx.x;
    int p0 = blockIdx.x * 32;
    int base = (p0 >> 12) * (DD * HW) + (p0 & 4095);

    for (int i = tid; i < 2048; i += 256) {
        int d = i >> 5, p = i & 31;
        sZ[d * 32 + p]        = x2r[base + d * HW + p];
        sZ[(64 + d) * 32 + p] = x2i[base + d * HW + p];
    }
    __syncthreads();
    {   // LN: 8 threads per position
        int p = tid >> 3, l = tid & 7;
        float sum = 0.f, sq = 0.f;
#pragma unroll
        for (int c = l; c < 128; c += 8) { float v = sZ[c * 32 + p]; sum += v; sq += v * v; }
#pragma unroll
        for (int m = 1; m < 8; m <<= 1) {
            sum += __shfl_xor_sync(0xffffffffu, sum, m);
            sq  += __shfl_xor_sync(0xffffffffu, sq,  m);
        }
        float mu = sum * (1.f / 128.f);
        float rs = rsqrtf(sq * (1.f / 128.f) - mu * mu + 1e-5f);
#pragma unroll
        for (int c = l; c < 128; c += 8) {
            float v = sZ[c * 32 + p];
            sZ[c * 32 + p] = (v - mu) * rs * lnw[c] + lnb[c];
        }
    }
    __syncthreads();
    {   // GEMM1 + gelu: thread = hidden unit j
        float acc[32];
#pragma unroll
        for (int p = 0; p < 32; p++) acc[p] = 0.f;
        int j = tid;
        for (int k = 0; k < 128; k++) {
            float wv = w1[k * 256 + j];
            const float2* zp = (const float2*)&sZ[k * 32];
#pragma unroll
            for (int q = 0; q < 16; q++) {
                float2 z2 = zp[q];
                acc[2 * q]     += z2.x * wv;
                acc[2 * q + 1] += z2.y * wv;
            }
        }
        float bb = b1[j];
#pragma unroll
        for (int p = 0; p < 32; p++) {
            float h = acc[p] + bb;
            h = 0.5f * h * (1.f + erff(h * 0.70710678118654752f));
            sH[p * 256 + j] = h;
        }
    }
    __syncthreads();
    float acc2[16];
    int o = tid & 127, pb = (tid >> 7) * 16;
    {   // GEMM2: thread = (out unit, half the positions)
#pragma unroll
        for (int q = 0; q < 16; q++) acc2[q] = 0.f;
        for (int k = 0; k < 256; k += 2) {
            float wv0 = w2[k * 128 + o];
            float wv1 = w2[(k + 1) * 128 + o];
#pragma unroll
            for (int q = 0; q < 16; q++) {
                float2 h2 = *(const float2*)&sH[(pb + q) * 256 + k];
                acc2[q] += h2.x * wv0 + h2.y * wv1;
            }
        }
        float bb = b2[o];
#pragma unroll
        for (int q = 0; q < 16; q++) acc2[q] += bb;
    }
    __syncthreads();
#pragma unroll
    for (int q = 0; q < 16; q++) smem[(pb + q) * 130 + o] = acc2[q];
    __syncthreads();
    for (int i = tid; i < 4096; i += 256) {
        int c = i >> 5, p = i & 31;
        int dd = c >> 1, comp = c & 1;
        int gi = base + dd * HW + p;
        float v = smem[p * 130 + (comp ? 64 + dd : dd)];
        out[2 * gi + comp] = v + (comp ? x2i[gi] : x2r[gi]);
    }
}

// -----------------------------------------------------------------------------
extern "C" void kernel_launch(void* const* d_in, const int* in_sizes, int n_in,
                              void* d_out, int out_size)
{
    (void)in_sizes; (void)n_in; (void)out_size;
    const float* x_real  = (const float*)d_in[0];
    const float* x_imag  = (const float*)d_in[1];
    const float* dt      = (const float*)d_in[2];
    const float* ln_s_w  = (const float*)d_in[3];
    const float* ln_s_b  = (const float*)d_in[4];
    const float* ln_t_w  = (const float*)d_in[5];
    const float* ln_t_b  = (const float*)d_in[6];
    const float* ln_m_w  = (const float*)d_in[7];
    const float* ln_m_b  = (const float*)d_in[8];
    const float* cw_r    = (const float*)d_in[9];
    const float* cw_i    = (const float*)d_in[10];
    const float* cb_r    = (const float*)d_in[11];
    const float* cb_i    = (const float*)d_in[12];
    const float* spec_wr = (const float*)d_in[13];
    const float* spec_wi = (const float*)d_in[14];
    const float* gate    = (const float*)d_in[15];
    const float* lam_re  = (const float*)d_in[16];
    const float* lam_im  = (const float*)d_in[17];
    const float* V_re    = (const float*)d_in[18];
    const float* V_im    = (const float*)d_in[19];
    const float* Vinv_re = (const float*)d_in[20];
    const float* Vinv_im = (const float*)d_in[21];
    const float* w1      = (const float*)d_in[22];
    const float* b1      = (const float*)d_in[23];
    const float* w2      = (const float*)d_in[24];
    const float* b2      = (const float*)d_in[25];
    float* out = (float*)d_out;

    float *xnr, *xni, *cr, *ci, *x1r, *x1i, *tnr, *tni, *er, *ei, *x2r, *x2i;
    float2* evo;
    cudaGetSymbolAddress((void**)&xnr, g_xnr);
    cudaGetSymbolAddress((void**)&xni, g_xni);
    cudaGetSymbolAddress((void**)&cr,  g_cr);
    cudaGetSymbolAddress((void**)&ci,  g_ci);
    cudaGetSymbolAddress((void**)&x1r, g_x1r);
    cudaGetSymbolAddress((void**)&x1i, g_x1i);
    cudaGetSymbolAddress((void**)&tnr, g_tnr);
    cudaGetSymbolAddress((void**)&tni, g_tni);
    cudaGetSymbolAddress((void**)&er,  g_er);
    cudaGetSymbolAddress((void**)&ei,  g_ei);
    cudaGetSymbolAddress((void**)&x2r, g_x2r);
    cudaGetSymbolAddress((void**)&x2i, g_x2i);
    cudaGetSymbolAddress((void**)&evo, g_evo);

    // ---- spatial stage ----
    cnorm_kernel<<<512, 256>>>(x_real, x_imag, ln_s_w, ln_s_b, xnr, xni);
    conv_kernel<<<dim3(4, 8, 32), dim3(16, 16)>>>(xnr, xni, cw_r, cw_i, cb_r, cb_i, cr, ci);
    spec_kernel<<<2048, 128>>>(xnr, xni, spec_wr, spec_wi, cr, ci,
                               x_real, x_imag, gate, x1r, x1i);
    // ---- temporal stage ----
    cnorm_kernel<<<512, 256>>>(x1r, x1i, ln_t_w, ln_t_b, tnr, tni);
    cproj_kernel<<<dim3(512, 4), 256>>>(tnr, tni, Vinv_re, Vinv_im,
                                        tnr, tni, er, ei, 0);
    evo_kernel<<<8, 256>>>(dt, lam_re, lam_im, evo);
    scan_kernel<<<2048, 256>>>(er, ei, evo);
    cproj_kernel<<<dim3(512, 4), 256>>>(er, ei, V_re, V_im,
                                        x1r, x1i, x2r, x2i, 1);
    // ---- MLP stage -> final interleaved output ----
    mlp_kernel<<<4096, 256>>>(x2r, x2i, ln_m_w, ln_m_b, w1, b1, w2, b2, out);
}

// round 13
// speedup vs baseline: 1.2917x; 1.1166x over previous
#include <cuda_runtime.h>
#include <cuda_bf16.h>

#define BB 2
#define TT 16
#define DD 64
#define HW 4096
#define NELEM 8388608   // B*T*D*H*W

typedef unsigned long long u64;

// ---------------- packed fp32x2 helpers (SASS FFMA2) --------------------------
__device__ __forceinline__ u64 pack2(float lo, float hi) {
    u64 r; asm("mov.b64 %0, {%1, %2};" : "=l"(r) : "f"(lo), "f"(hi)); return r;
}
__device__ __forceinline__ u64 pdup(float v) { return pack2(v, v); }
__device__ __forceinline__ float2 unpk(u64 v) {
    float2 f; asm("mov.b64 {%0, %1}, %2;" : "=f"(f.x), "=f"(f.y) : "l"(v)); return f;
}
__device__ __forceinline__ u64 ffma2(u64 a, u64 b, u64 c) {
    u64 d; asm("fma.rn.f32x2 %0, %1, %2, %3;" : "=l"(d) : "l"(a), "l"(b), "l"(c)); return d;
}

// ---------------- scratch (device globals; no allocation allowed) -------------
__device__ float g_xnr[NELEM], g_xni[NELEM];
__device__ float g_cr [NELEM], g_ci [NELEM];
__device__ float g_x1r[NELEM], g_x1i[NELEM];
__device__ float g_tnr[NELEM], g_tni[NELEM];
__device__ float g_er [NELEM], g_ei [NELEM];
__device__ float g_x2r[NELEM], g_x2i[NELEM];
__device__ float2 g_evo[BB*TT*DD];

// ---------------- complex layernorm over 128 feats per (bt,hw) ---------------
__global__ void cnorm_kernel(const float* __restrict__ inr, const float* __restrict__ ini,
                             const float* __restrict__ w,   const float* __restrict__ b,
                             float* __restrict__ outr, float* __restrict__ outi)
{
    int p = blockIdx.x * blockDim.x + threadIdx.x;
    int base = (p >> 12) * (DD * HW) + (p & 4095);
    float sum = 0.f, sq = 0.f;
#pragma unroll 8
    for (int d = 0; d < DD; d++) {
        float a = inr[base + d * HW], c = ini[base + d * HW];
        sum += a + c; sq += a * a + c * c;
    }
    float mu = sum * (1.f / 128.f);
    float rs = rsqrtf(sq * (1.f / 128.f) - mu * mu + 1e-5f);
#pragma unroll 8
    for (int d = 0; d < DD; d++) {
        float a = inr[base + d * HW], c = ini[base + d * HW];
        outr[base + d * HW] = (a - mu) * rs * w[d]      + b[d];
        outi[base + d * HW] = (c - mu) * rs * w[DD + d] + b[DD + d];
    }
}

// ---------------- Clifford complex 3x3 conv, 64->64 ch (FFMA2) ---------------
// tile = 16 rows x 64 cols; thread owns row ty, cols 4tx..4tx+3, 8 oc.
__global__ void __launch_bounds__(256) conv_kernel(
                            const float* __restrict__ xr, const float* __restrict__ xi,
                            const float* __restrict__ wr, const float* __restrict__ wi,
                            const float* __restrict__ br, const float* __restrict__ bi,
                            float* __restrict__ outr, float* __restrict__ outi)
{
    __shared__ float2 s_in[18 * 66];
    __shared__ ulonglong2 s_w[8 * 9];   // {(w.re,w.im),(-w.im,w.re)} per (oc,tap)
    int h0  = blockIdx.x * 16;
    int oc0 = blockIdx.y * 8;
    int bt  = blockIdx.z;
    int tx = threadIdx.x, ty = threadIdx.y;
    int tid = ty * 16 + tx;

    u64 acc[8][4];
#pragma unroll
    for (int o = 0; o < 8; o++)
#pragma unroll
        for (int p = 0; p < 4; p++) acc[o][p] = 0ull;

    for (int ic = 0; ic < 64; ic++) {
        const float* pr = xr + (bt * 64 + ic) * HW;
        const float* pi = xi + (bt * 64 + ic) * HW;
        for (int idx = tid; idx < 18 * 66; idx += 256) {
            int r = idx / 66, c = idx - r * 66;
            int gh = h0 - 1 + r, gw = c - 1;
            float vr = 0.f, vi = 0.f;
            if ((unsigned)gh < 64u && (unsigned)gw < 64u) {
                int g = gh * 64 + gw; vr = pr[g]; vi = pi[g];
            }
            s_in[idx] = make_float2(vr, vi);
        }
        if (tid < 72) {
            int o = tid / 9, k = tid - o * 9;
            int widx = ((oc0 + o) * 64 + ic) * 9 + k;
            float wre = wr[widx], wim = wi[widx];
            s_w[tid] = make_ulonglong2(pack2(wre, wim), pack2(-wim, wre));
        }
        __syncthreads();
#pragma unroll
        for (int ky = 0; ky < 3; ky++) {
            const float4* rowp = (const float4*)&s_in[(ty + ky) * 66 + 4 * tx];
            float4 q0 = rowp[0], q1 = rowp[1], q2 = rowp[2];
            u64 ax[6], ay[6];
            ax[0] = pdup(q0.x); ay[0] = pdup(q0.y);
            ax[1] = pdup(q0.z); ay[1] = pdup(q0.w);
            ax[2] = pdup(q1.x); ay[2] = pdup(q1.y);
            ax[3] = pdup(q1.z); ay[3] = pdup(q1.w);
            ax[4] = pdup(q2.x); ay[4] = pdup(q2.y);
            ax[5] = pdup(q2.z); ay[5] = pdup(q2.w);
#pragma unroll
            for (int kx = 0; kx < 3; kx++) {
#pragma unroll
                for (int o = 0; o < 8; o++) {
                    ulonglong2 wq = s_w[o * 9 + ky * 3 + kx];
#pragma unroll
                    for (int p = 0; p < 4; p++) {
                        acc[o][p] = ffma2(ax[p + kx], wq.x, acc[o][p]);
                        acc[o][p] = ffma2(ay[p + kx], wq.y, acc[o][p]);
                    }
                }
            }
        }
        __syncthreads();
    }
    int opos = (h0 + ty) * 64 + 4 * tx;
#pragma unroll
    for (int o = 0; o < 8; o++) {
        float bre = br[oc0 + o], bim = bi[oc0 + o];
        int gi = (bt * 64 + oc0 + o) * HW + opos;
        float2 v0 = unpk(acc[o][0]), v1 = unpk(acc[o][1]);
        float2 v2 = unpk(acc[o][2]), v3 = unpk(acc[o][3]);
        *(float4*)&outr[gi] = make_float4(v0.x + bre, v1.x + bre, v2.x + bre, v3.x + bre);
        *(float4*)&outi[gi] = make_float4(v0.y + bim, v1.y + bim, v2.y + bim, v3.y + bim);
    }
}

// ---------------- 64-pt DFT pass, packed twiddles (FFMA2) --------------------
template<int AXIS>
__device__ __forceinline__ void dft_pass(float* sRe, float* sIm, const ulonglong2* tw,
                                         int a, int jbase, float scale)
{
    u64 acc[32];
#pragma unroll
    for (int j = 0; j < 32; j++) acc[j] = 0ull;
    for (int k = 0; k < 64; k++) {
        float vr = (AXIS == 0) ? sRe[a * 65 + k] : sRe[k * 65 + a];
        float vi = (AXIS == 0) ? sIm[a * 65 + k] : sIm[k * 65 + a];
        u64 vr2 = pdup(vr), vi2 = pdup(vi);
#pragma unroll
        for (int j = 0; j < 32; j++) {
            ulonglong2 w = tw[((jbase + j) * k) & 63];   // uniform across warp
            acc[j] = ffma2(vr2, w.x, acc[j]);
            acc[j] = ffma2(vi2, w.y, acc[j]);
        }
    }
    __syncthreads();
#pragma unroll
    for (int j = 0; j < 32; j++) {
        int jj = jbase + j;
        float2 v = unpk(acc[j]);
        if (AXIS == 0) { sRe[a * 65 + jj] = v.x * scale; sIm[a * 65 + jj] = v.y * scale; }
        else           { sRe[jj * 65 + a] = v.x * scale; sIm[jj * 65 + a] = v.y * scale; }
    }
    __syncthreads();
}

__global__ void __launch_bounds__(128) spec_kernel(
                            const float* __restrict__ xnr, const float* __restrict__ xni,
                            const float* __restrict__ swr, const float* __restrict__ swi,
                            const float* __restrict__ clr, const float* __restrict__ cli,
                            const float* __restrict__ x0r, const float* __restrict__ x0i,
                            const float* __restrict__ gate,
                            float* __restrict__ outr, float* __restrict__ outi)
{
    __shared__ float sRe[64 * 65];
    __shared__ float sIm[64 * 65];
    __shared__ ulonglong2 stwF[64], stwI[64];
    int tid = threadIdx.x;
    int warp = tid >> 5, lane = tid & 31;
    int a = lane + 32 * (warp >> 1);
    int jbase = (warp & 1) * 32;
    int bd = blockIdx.x;
    int d = bd & 63;
    int base = bd * HW;

    if (tid < 64) {
        float s, c;
        sincospif((float)tid * (1.f / 32.f), &s, &c);
        // forward: pair1=(c,-s), pair2=(s,c); inverse: pair1=(c,s), pair2=(-s,c)
        stwF[tid] = make_ulonglong2(pack2(c, -s), pack2(s, c));
        stwI[tid] = make_ulonglong2(pack2(c, s), pack2(-s, c));
    }
    for (int i = tid; i < 4096; i += 128) {
        int r = i >> 6, c = i & 63;
        sRe[r * 65 + c] = xnr[base + i];
        sIm[r * 65 + c] = xni[base + i];
    }
    __syncthreads();

    dft_pass<0>(sRe, sIm, stwF, a, jbase, 1.f);
    dft_pass<1>(sRe, sIm, stwF, a, jbase, 1.f);

    for (int i = tid; i < 4096; i += 128) {
        int r = i >> 6, c = i & 63;
        float vr = sRe[r * 65 + c], vi = sIm[r * 65 + c];
        float wrv = swr[d * HW + i], wiv = swi[d * HW + i];
        sRe[r * 65 + c] = vr * wrv - vi * wiv;
        sIm[r * 65 + c] = vr * wiv + vi * wrv;
    }
    __syncthreads();

    dft_pass<1>(sRe, sIm, stwI, a, jbase, 1.f / 64.f);
    dft_pass<0>(sRe, sIm, stwI, a, jbase, 1.f / 64.f);

    float g = gate[0], og = 1.f - g;
    for (int i = tid; i < 4096; i += 128) {
        int r = i >> 6, c = i & 63;
        int gi = base + i;
        outr[gi] = g * clr[gi] + og * sRe[r * 65 + c] + x0r[gi];
        outi[gi] = g * cli[gi] + og * sIm[r * 65 + c] + x0i[gi];
    }
}

// ---------------- complex projection (FFMA2) ---------------------------------
__global__ void cproj_kernel(const float* __restrict__ xr, const float* __restrict__ xi,
                             const float* __restrict__ Mre, const float* __restrict__ Mim,
                             const float* __restrict__ resr, const float* __restrict__ resi,
                             float* __restrict__ outr, float* __restrict__ outi,
                             int add_resid)
{
    __shared__ ulonglong2 sM[16 * 64];
    int tid = threadIdx.x;
    int oc0 = blockIdx.y * 16;
    for (int i = tid; i < 1024; i += 256) {
        int o = i >> 6, k = i & 63;
        float mre = Mre[(oc0 + o) * 64 + k], mim = Mim[(oc0 + o) * 64 + k];
        sM[i] = make_ulonglong2(pack2(mre, mim), pack2(-mim, mre));
    }
    __syncthreads();
    int p = blockIdx.x * 256 + tid;
    int base = (p >> 12) * (DD * HW) + (p & 4095);
    u64 acc[16];
#pragma unroll
    for (int o = 0; o < 16; o++) acc[o] = 0ull;
    for (int k = 0; k < 64; k++) {
        u64 a2 = pdup(xr[base + k * HW]);
        u64 c2 = pdup(xi[base + k * HW]);
#pragma unroll
        for (int o = 0; o < 16; o++) {
            ulonglong2 m = sM[o * 64 + k];
            acc[o] = ffma2(a2, m.x, acc[o]);
            acc[o] = ffma2(c2, m.y, acc[o]);
        }
    }
#pragma unroll
    for (int o = 0; o < 16; o++) {
        int gi = base + (oc0 + o) * HW;
        float2 v = unpk(acc[o]);
        if (add_resid) { v.x += resr[gi]; v.y += resi[gi]; }
        outr[gi] = v.x; outi[gi] = v.y;
    }
}

// ---------------- evo = exp(lam * dt) ----------------------------------------
__global__ void evo_kernel(const float* __restrict__ dt,
                           const float* __restrict__ lam_re, const float* __restrict__ lam_im,
                           float2* __restrict__ evo)
{
    int i = blockIdx.x * blockDim.x + threadIdx.x;
    if (i >= BB * TT * DD) return;
    int d = i & 63;
    int b = i >> 10, t = (i >> 6) & 15;
    float dtv = dt[b * 16 + t];
    float lre = -log1pf(expf(lam_re[d]));
    float m = expf(lre * dtv);
    float s, c;
    sincosf(lam_im[d] * dtv, &s, &c);
    evo[i] = make_float2(m * c, m * s);
}

// ---------------- diagonal temporal scan over T=16, in place -----------------
__global__ void scan_kernel(float* __restrict__ er, float* __restrict__ ei,
                            const float2* __restrict__ evo)
{
    int idx = blockIdx.x * 256 + threadIdx.x;
    int b = idx >> 18;
    int dhw = idx & 262143;
    int d = dhw >> 12;
    float hr = 0.f, hi = 0.f;
#pragma unroll
    for (int t = 0; t < 16; t++) {
        float2 a = evo[(b * 16 + t) * 64 + d];
        int gi = (b * 16 + t) * (DD * HW) + dhw;
        float xr = er[gi], xv = ei[gi];
        float nr = a.x * hr - a.y * hi + xr;
        float ni = a.x * hi + a.y * hr + xv;
        hr = nr; hi = ni;
        er[gi] = hr; ei[gi] = hi;
    }
}

// ---------------- fused LN + MLP(128->256 gelu ->128) + resid (FFMA2) --------
__global__ void mlp_kernel(const float* __restrict__ x2r, const float* __restrict__ x2i,
                           const float* __restrict__ lnw, const float* __restrict__ lnb,
                           const float* __restrict__ w1,  const float* __restrict__ b1,
                           const float* __restrict__ w2,  const float* __restrict__ b2,
                           float* __restrict__ out)
{
    __shared__ __align__(16) float smem[12288];  // 48 KB
    float* sZ = smem;            // [128 feat][32 pos]
    float* sH = smem + 4096;     // [32 pos][256 hid]
    int tid = threadIdx.x;
    int p0 = blockIdx.x * 32;
    int base = (p0 >> 12) * (DD * HW) + (p0 & 4095);

    for (int i = tid; i < 2048; i += 256) {
        int d = i >> 5, p = i & 31;
        sZ[d * 32 + p]        = x2r[base + d * HW + p];
        sZ[(64 + d) * 32 + p] = x2i[base + d * HW + p];
    }
    __syncthreads();
    {   // LN: 8 threads per position
        int p = tid >> 3, l = tid & 7;
        float sum = 0.f, sq = 0.f;
#pragma unroll
        for (int c = l; c < 128; c += 8) { float v = sZ[c * 32 + p]; sum += v; sq += v * v; }
#pragma unroll
        for (int m = 1; m < 8; m <<= 1) {
            sum += __shfl_xor_sync(0xffffffffu, sum, m);
            sq  += __shfl_xor_sync(0xffffffffu, sq,  m);
        }
        float mu = sum * (1.f / 128.f);
        float rs = rsqrtf(sq * (1.f / 128.f) - mu * mu + 1e-5f);
#pragma unroll
        for (int c = l; c < 128; c += 8) {
            float v = sZ[c * 32 + p];
            sZ[c * 32 + p] = (v - mu) * rs * lnw[c] + lnb[c];
        }
    }
    __syncthreads();
    {   // GEMM1 + gelu: thread = hidden unit j, packed position-pairs
        u64 acc[16];
#pragma unroll
        for (int q = 0; q < 16; q++) acc[q] = 0ull;
        int j = tid;
        for (int k = 0; k < 128; k++) {
            u64 wv2 = pdup(w1[k * 256 + j]);
            const u64* zp = (const u64*)&sZ[k * 32];
#pragma unroll
            for (int q = 0; q < 16; q++)
                acc[q] = ffma2(zp[q], wv2, acc[q]);
        }
        float bb = b1[j];
#pragma unroll
        for (int q = 0; q < 16; q++) {
            float2 v = unpk(acc[q]);
            float h0 = v.x + bb, h1 = v.y + bb;
            h0 = 0.5f * h0 * (1.f + erff(h0 * 0.70710678118654752f));
            h1 = 0.5f * h1 * (1.f + erff(h1 * 0.70710678118654752f));
            sH[(2 * q) * 256 + j]     = h0;
            sH[(2 * q + 1) * 256 + j] = h1;
        }
    }
    __syncthreads();
    // GEMM2: thread = (output pair 2op,2op+1; group of 8 positions), packed outputs
    int op = tid & 63;            // output pair index 0..63
    int pg = (tid >> 6) * 8;      // position group base
    u64 acc2[8];
    {
#pragma unroll
        for (int q = 0; q < 8; q++) acc2[q] = 0ull;
        const float2* w2p = (const float2*)w2;     // w2[k][128]: pair (2op,2op+1)
        for (int k = 0; k < 256; k++) {
            float2 wp = w2p[k * 64 + op];
            u64 wv = pack2(wp.x, wp.y);
#pragma unroll
            for (int q = 0; q < 8; q++) {
                u64 h2 = pdup(sH[(pg + q) * 256 + k]);   // broadcast
                acc2[q] = ffma2(h2, wv, acc2[q]);
            }
        }
    }
    __syncthreads();   // sH dead
    {
        float bx = b2[2 * op], by = b2[2 * op + 1];
#pragma unroll
        for (int q = 0; q < 8; q++) {
            float2 v = unpk(acc2[q]);
            *(u64*)&smem[(pg + q) * 130 + 2 * op] = pack2(v.x + bx, v.y + by);
        }
    }
    __syncthreads();
    for (int i = tid; i < 4096; i += 256) {
        int c = i >> 5, p = i & 31;
        int dd = c >> 1, comp = c & 1;
        int gi = base + dd * HW + p;
        float v = smem[p * 130 + (comp ? 64 + dd : dd)];
        out[2 * gi + comp] = v + (comp ? x2i[gi] : x2r[gi]);
    }
}

// -----------------------------------------------------------------------------
extern "C" void kernel_launch(void* const* d_in, const int* in_sizes, int n_in,
                              void* d_out, int out_size)
{
    (void)in_sizes; (void)n_in; (void)out_size;
    const float* x_real  = (const float*)d_in[0];
    const float* x_imag  = (const float*)d_in[1];
    const float* dt      = (const float*)d_in[2];
    const float* ln_s_w  = (const float*)d_in[3];
    const float* ln_s_b  = (const float*)d_in[4];
    const float* ln_t_w  = (const float*)d_in[5];
    const float* ln_t_b  = (const float*)d_in[6];
    const float* ln_m_w  = (const float*)d_in[7];
    const float* ln_m_b  = (const float*)d_in[8];
    const float* cw_r    = (const float*)d_in[9];
    const float* cw_i    = (const float*)d_in[10];
    const float* cb_r    = (const float*)d_in[11];
    const float* cb_i    = (const float*)d_in[12];
    const float* spec_wr = (const float*)d_in[13];
    const float* spec_wi = (const float*)d_in[14];
    const float* gate    = (const float*)d_in[15];
    const float* lam_re  = (const float*)d_in[16];
    const float* lam_im  = (const float*)d_in[17];
    const float* V_re    = (const float*)d_in[18];
    const float* V_im    = (const float*)d_in[19];
    const float* Vinv_re = (const float*)d_in[20];
    const float* Vinv_im = (const float*)d_in[21];
    const float* w1      = (const float*)d_in[22];
    const float* b1      = (const float*)d_in[23];
    const float* w2      = (const float*)d_in[24];
    const float* b2      = (const float*)d_in[25];
    float* out = (float*)d_out;

    float *xnr, *xni, *cr, *ci, *x1r, *x1i, *tnr, *tni, *er, *ei, *x2r, *x2i;
    float2* evo;
    cudaGetSymbolAddress((void**)&xnr, g_xnr);
    cudaGetSymbolAddress((void**)&xni, g_xni);
    cudaGetSymbolAddress((void**)&cr,  g_cr);
    cudaGetSymbolAddress((void**)&ci,  g_ci);
    cudaGetSymbolAddress((void**)&x1r, g_x1r);
    cudaGetSymbolAddress((void**)&x1i, g_x1i);
    cudaGetSymbolAddress((void**)&tnr, g_tnr);
    cudaGetSymbolAddress((void**)&tni, g_tni);
    cudaGetSymbolAddress((void**)&er,  g_er);
    cudaGetSymbolAddress((void**)&ei,  g_ei);
    cudaGetSymbolAddress((void**)&x2r, g_x2r);
    cudaGetSymbolAddress((void**)&x2i, g_x2i);
    cudaGetSymbolAddress((void**)&evo, g_evo);

    // ---- spatial stage ----
    cnorm_kernel<<<512, 256>>>(x_real, x_imag, ln_s_w, ln_s_b, xnr, xni);
    conv_kernel<<<dim3(4, 8, 32), dim3(16, 16)>>>(xnr, xni, cw_r, cw_i, cb_r, cb_i, cr, ci);
    spec_kernel<<<2048, 128>>>(xnr, xni, spec_wr, spec_wi, cr, ci,
                               x_real, x_imag, gate, x1r, x1i);
    // ---- temporal stage ----
    cnorm_kernel<<<512, 256>>>(x1r, x1i, ln_t_w, ln_t_b, tnr, tni);
    cproj_kernel<<<dim3(512, 4), 256>>>(tnr, tni, Vinv_re, Vinv_im,
                                        tnr, tni, er, ei, 0);
    evo_kernel<<<8, 256>>>(dt, lam_re, lam_im, evo);
    scan_kernel<<<2048, 256>>>(er, ei, evo);
    cproj_kernel<<<dim3(512, 4), 256>>>(er, ei, V_re, V_im,
                                        x1r, x1i, x2r, x2i, 1);
    // ---- MLP stage -> final interleaved output ----
    mlp_kernel<<<4096, 256>>>(x2r, x2i, ln_m_w, ln_m_b, w1, b1, w2, b2, out);
}

// round 15
// speedup vs baseline: 1.6534x; 1.2800x over previous
#include <cuda_runtime.h>
#include <cuda_bf16.h>

#define BB 2
#define TT 16
#define DD 64
#define HW 4096
#define NELEM 8388608   // B*T*D*H*W

typedef unsigned long long u64;

// ---------------- packed fp32x2 helpers (SASS FFMA2) --------------------------
__device__ __forceinline__ u64 pack2(float lo, float hi) {
    u64 r; asm("mov.b64 %0, {%1, %2};" : "=l"(r) : "f"(lo), "f"(hi)); return r;
}
__device__ __forceinline__ u64 pdup(float v) { return pack2(v, v); }
__device__ __forceinline__ float2 unpk(u64 v) {
    float2 f; asm("mov.b64 {%0, %1}, %2;" : "=f"(f.x), "=f"(f.y) : "l"(v)); return f;
}
__device__ __forceinline__ u64 ffma2(u64 a, u64 b, u64 c) {
    u64 d; asm("fma.rn.f32x2 %0, %1, %2, %3;" : "=l"(d) : "l"(a), "l"(b), "l"(c)); return d;
}

// ---------------- scratch (device globals; no allocation allowed) -------------
__device__ float g_xnr[NELEM], g_xni[NELEM];
__device__ float g_cr [NELEM], g_ci [NELEM];
__device__ float g_x1r[NELEM], g_x1i[NELEM];
__device__ float g_tnr[NELEM], g_tni[NELEM];
__device__ float g_er [NELEM], g_ei [NELEM];
__device__ float g_x2r[NELEM], g_x2i[NELEM];
__device__ float2 g_evo[BB*TT*DD];

// ---------------- complex layernorm over 128 feats per (bt,hw) ---------------
__global__ void cnorm_kernel(const float* __restrict__ inr, const float* __restrict__ ini,
                             const float* __restrict__ w,   const float* __restrict__ b,
                             float* __restrict__ outr, float* __restrict__ outi)
{
    int p = blockIdx.x * blockDim.x + threadIdx.x;
    int base = (p >> 12) * (DD * HW) + (p & 4095);
    float sum = 0.f, sq = 0.f;
#pragma unroll 8
    for (int d = 0; d < DD; d++) {
        float a = inr[base + d * HW], c = ini[base + d * HW];
        sum += a + c; sq += a * a + c * c;
    }
    float mu = sum * (1.f / 128.f);
    float rs = rsqrtf(sq * (1.f / 128.f) - mu * mu + 1e-5f);
#pragma unroll 8
    for (int d = 0; d < DD; d++) {
        float a = inr[base + d * HW], c = ini[base + d * HW];
        outr[base + d * HW] = (a - mu) * rs * w[d]      + b[d];
        outi[base + d * HW] = (c - mu) * rs * w[DD + d] + b[DD + d];
    }
}

// ---------------- Clifford complex 3x3 conv, 64->64 ch (FFMA2) ---------------
__global__ void __launch_bounds__(256) conv_kernel(
                            const float* __restrict__ xr, const float* __restrict__ xi,
                            const float* __restrict__ wr, const float* __restrict__ wi,
                            const float* __restrict__ br, const float* __restrict__ bi,
                            float* __restrict__ outr, float* __restrict__ outi)
{
    __shared__ float2 s_in[18 * 66];
    __shared__ ulonglong2 s_w[8 * 9];
    int h0  = blockIdx.x * 16;
    int oc0 = blockIdx.y * 8;
    int bt  = blockIdx.z;
    int tx = threadIdx.x, ty = threadIdx.y;
    int tid = ty * 16 + tx;

    u64 acc[8][4];
#pragma unroll
    for (int o = 0; o < 8; o++)
#pragma unroll
        for (int p = 0; p < 4; p++) acc[o][p] = 0ull;

    for (int ic = 0; ic < 64; ic++) {
        const float* pr = xr + (bt * 64 + ic) * HW;
        const float* pi = xi + (bt * 64 + ic) * HW;
        for (int idx = tid; idx < 18 * 66; idx += 256) {
            int r = idx / 66, c = idx - r * 66;
            int gh = h0 - 1 + r, gw = c - 1;
            float vr = 0.f, vi = 0.f;
            if ((unsigned)gh < 64u && (unsigned)gw < 64u) {
                int g = gh * 64 + gw; vr = pr[g]; vi = pi[g];
            }
            s_in[idx] = make_float2(vr, vi);
        }
        if (tid < 72) {
            int o = tid / 9, k = tid - o * 9;
            int widx = ((oc0 + o) * 64 + ic) * 9 + k;
            float wre = wr[widx], wim = wi[widx];
            s_w[tid] = make_ulonglong2(pack2(wre, wim), pack2(-wim, wre));
        }
        __syncthreads();
#pragma unroll
        for (int ky = 0; ky < 3; ky++) {
            const float4* rowp = (const float4*)&s_in[(ty + ky) * 66 + 4 * tx];
            float4 q0 = rowp[0], q1 = rowp[1], q2 = rowp[2];
            u64 ax[6], ay[6];
            ax[0] = pdup(q0.x); ay[0] = pdup(q0.y);
            ax[1] = pdup(q0.z); ay[1] = pdup(q0.w);
            ax[2] = pdup(q1.x); ay[2] = pdup(q1.y);
            ax[3] = pdup(q1.z); ay[3] = pdup(q1.w);
            ax[4] = pdup(q2.x); ay[4] = pdup(q2.y);
            ax[5] = pdup(q2.z); ay[5] = pdup(q2.w);
#pragma unroll
            for (int kx = 0; kx < 3; kx++) {
#pragma unroll
                for (int o = 0; o < 8; o++) {
                    ulonglong2 wq = s_w[o * 9 + ky * 3 + kx];
#pragma unroll
                    for (int p = 0; p < 4; p++) {
                        acc[o][p] = ffma2(ax[p + kx], wq.x, acc[o][p]);
                        acc[o][p] = ffma2(ay[p + kx], wq.y, acc[o][p]);
                    }
                }
            }
        }
        __syncthreads();
    }
    int opos = (h0 + ty) * 64 + 4 * tx;
#pragma unroll
    for (int o = 0; o < 8; o++) {
        float bre = br[oc0 + o], bim = bi[oc0 + o];
        int gi = (bt * 64 + oc0 + o) * HW + opos;
        float2 v0 = unpk(acc[o][0]), v1 = unpk(acc[o][1]);
        float2 v2 = unpk(acc[o][2]), v3 = unpk(acc[o][3]);
        *(float4*)&outr[gi] = make_float4(v0.x + bre, v1.x + bre, v2.x + bre, v3.x + bre);
        *(float4*)&outi[gi] = make_float4(v0.y + bim, v1.y + bim, v2.y + bim, v3.y + bim);
    }
}

// ---------------- radix-8 FFT pieces -----------------------------------------
// DIF 8-point DFT: natural input, natural-order output (brev folded into stores).
// SGN = -1 forward (e^{-i}), +1 inverse.
template<int SGN>
__device__ __forceinline__ void dft8(const float2* a, float2* X)
{
    const float C = 0.70710678118654752f;
    float2 b0 = make_float2(a[0].x + a[4].x, a[0].y + a[4].y);
    float2 b1 = make_float2(a[1].x + a[5].x, a[1].y + a[5].y);
    float2 b2 = make_float2(a[2].x + a[6].x, a[2].y + a[6].y);
    float2 b3 = make_float2(a[3].x + a[7].x, a[3].y + a[7].y);
    float2 d0 = make_float2(a[0].x - a[4].x, a[0].y - a[4].y);
    float2 d1 = make_float2(a[1].x - a[5].x, a[1].y - a[5].y);
    float2 d2 = make_float2(a[2].x - a[6].x, a[2].y - a[6].y);
    float2 d3 = make_float2(a[3].x - a[7].x, a[3].y - a[7].y);
    float2 b4 = d0;
    float2 b5 = make_float2(C * (d1.x - SGN * d1.y), C * (d1.y + SGN * d1.x));
    float2 b6 = make_float2(-SGN * d2.y, SGN * d2.x);
    float2 b7 = make_float2(C * (-d3.x - SGN * d3.y), C * (-d3.y + SGN * d3.x));

    float2 c0 = make_float2(b0.x + b2.x, b0.y + b2.y);
    float2 c1 = make_float2(b1.x + b3.x, b1.y + b3.y);
    float2 e0 = make_float2(b0.x - b2.x, b0.y - b2.y);
    float2 e1 = make_float2(b1.x - b3.x, b1.y - b3.y);
    float2 c2 = e0;
    float2 c3 = make_float2(-SGN * e1.y, SGN * e1.x);
    float2 c4 = make_float2(b4.x + b6.x, b4.y + b6.y);
    float2 c5 = make_float2(b5.x + b7.x, b5.y + b7.y);
    float2 e2 = make_float2(b4.x - b6.x, b4.y - b6.y);
    float2 e3 = make_float2(b5.x - b7.x, b5.y - b7.y);
    float2 c6 = e2;
    float2 c7 = make_float2(-SGN * e3.y, SGN * e3.x);

    X[0] = make_float2(c0.x + c1.x, c0.y + c1.y);
    X[4] = make_float2(c0.x - c1.x, c0.y - c1.y);
    X[2] = make_float2(c2.x + c3.x, c2.y + c3.y);
    X[6] = make_float2(c2.x - c3.x, c2.y - c3.y);
    X[1] = make_float2(c4.x + c5.x, c4.y + c5.y);
    X[5] = make_float2(c4.x - c5.x, c4.y - c5.y);
    X[3] = make_float2(c6.x + c7.x, c6.y + c7.y);
    X[7] = make_float2(c6.x - c7.x, c6.y - c7.y);
}

// One 64-pt FFT pass over all 64 lines of a 64x64 plane in smem (pitch 72).
// AXIS 0: line = row (slot addr = line*72 + s); AXIS 1: line = col (s*72 + line).
// 8 threads per line: thread t = n1. tw[j] = e^{SGN*2*pi*i*j/64}.
// Exchange transpose uses XOR-rotation slots (all within [0,64)):
//   write B[t][k2]  at slot  k2*8 + ((t + k2) & 7)
//   read  B[n1][t]  at slot  t*8  + ((n1 + t) & 7)
template<int AXIS, int SGN>
__device__ __forceinline__ void fft_pass(float* sRe, float* sIm, const float2* tw,
                                         int line, int t, float scale)
{
#define SLOT(s) ((AXIS == 0) ? (line * 72 + (s)) : ((s) * 72 + line))
    float2 v[8], y[8];
#pragma unroll
    for (int n2 = 0; n2 < 8; n2++) {
        int s = t + 8 * n2;
        v[n2] = make_float2(sRe[SLOT(s)], sIm[SLOT(s)]);
    }
    dft8<SGN>(v, y);
#pragma unroll
    for (int k2 = 1; k2 < 8; k2++) {        // y[k2] *= tw[t*k2]
        float2 w = tw[t * k2];
        float re = y[k2].x * w.x - y[k2].y * w.y;
        float im = y[k2].x * w.y + y[k2].y * w.x;
        y[k2] = make_float2(re, im);
    }
    __syncthreads();                        // all initial reads done
#pragma unroll
    for (int k2 = 0; k2 < 8; k2++) {
        int s = k2 * 8 + ((t + k2) & 7);
        sRe[SLOT(s)] = y[k2].x; sIm[SLOT(s)] = y[k2].y;
    }
    __syncthreads();
    float2 z[8], Y[8];
#pragma unroll
    for (int n1 = 0; n1 < 8; n1++) {
        int s = t * 8 + ((n1 + t) & 7);
        z[n1] = make_float2(sRe[SLOT(s)], sIm[SLOT(s)]);
    }
    dft8<SGN>(z, Y);
    __syncthreads();                        // all exchange reads done
#pragma unroll
    for (int k1 = 0; k1 < 8; k1++) {        // final: X[t + 8*k1] (t plays k2)
        int s = t + 8 * k1;
        sRe[SLOT(s)] = Y[k1].x * scale; sIm[SLOT(s)] = Y[k1].y * scale;
    }
    __syncthreads();
#undef SLOT
}

// spectral mix (fft2 * wspec -> ifft2) fused with gated combine + residual.
// block per (bt,d) plane, 512 threads = 64 lines x 8.
__global__ void __launch_bounds__(512) spec_kernel(
                            const float* __restrict__ xnr, const float* __restrict__ xni,
                            const float* __restrict__ swr, const float* __restrict__ swi,
                            const float* __restrict__ clr, const float* __restrict__ cli,
                            const float* __restrict__ x0r, const float* __restrict__ x0i,
                            const float* __restrict__ gate,
                            float* __restrict__ outr, float* __restrict__ outi)
{
    __shared__ float sRe[64 * 72];
    __shared__ float sIm[64 * 72];
    __shared__ float2 stwF[64], stwI[64];
    int tid = threadIdx.x;
    int t = tid & 7, line = tid >> 3;
    int bd = blockIdx.x;
    int d = bd & 63;
    int base = bd * HW;

    if (tid < 64) {
        float s, c;
        sincospif((float)tid * (1.f / 32.f), &s, &c);   // 2*pi*tid/64
        stwF[tid] = make_float2(c, -s);
        stwI[tid] = make_float2(c, s);
    }
    for (int i = tid; i < 4096; i += 512) {
        int r = i >> 6, c = i & 63;
        sRe[r * 72 + c] = xnr[base + i];
        sIm[r * 72 + c] = xni[base + i];
    }
    __syncthreads();

    fft_pass<0, -1>(sRe, sIm, stwF, line, t, 1.f);     // fft along W
    fft_pass<1, -1>(sRe, sIm, stwF, line, t, 1.f);     // fft along H

    for (int i = tid; i < 4096; i += 512) {
        int r = i >> 6, c = i & 63;
        float vr = sRe[r * 72 + c], vi = sIm[r * 72 + c];
        float wrv = swr[d * HW + i], wiv = swi[d * HW + i];
        sRe[r * 72 + c] = vr * wrv - vi * wiv;
        sIm[r * 72 + c] = vr * wiv + vi * wrv;
    }
    __syncthreads();

    fft_pass<1, 1>(sRe, sIm, stwI, line, t, 1.f / 64.f);  // ifft along H
    fft_pass<0, 1>(sRe, sIm, stwI, line, t, 1.f / 64.f);  // ifft along W

    float g = gate[0], og = 1.f - g;
    for (int i = tid; i < 4096; i += 512) {
        int r = i >> 6, c = i & 63;
        int gi = base + i;
        outr[gi] = g * clr[gi] + og * sRe[r * 72 + c] + x0r[gi];
        outi[gi] = g * cli[gi] + og * sIm[r * 72 + c] + x0i[gi];
    }
}

// ---------------- complex projection (FFMA2) ---------------------------------
__global__ void cproj_kernel(const float* __restrict__ xr, const float* __restrict__ xi,
                             const float* __restrict__ Mre, const float* __restrict__ Mim,
                             const float* __restrict__ resr, const float* __restrict__ resi,
                             float* __restrict__ outr, float* __restrict__ outi,
                             int add_resid)
{
    __shared__ ulonglong2 sM[16 * 64];
    int tid = threadIdx.x;
    int oc0 = blockIdx.y * 16;
    for (int i = tid; i < 1024; i += 256) {
        int o = i >> 6, k = i & 63;
        float mre = Mre[(oc0 + o) * 64 + k], mim = Mim[(oc0 + o) * 64 + k];
        sM[i] = make_ulonglong2(pack2(mre, mim), pack2(-mim, mre));
    }
    __syncthreads();
    int p = blockIdx.x * 256 + tid;
    int base = (p >> 12) * (DD * HW) + (p & 4095);
    u64 acc[16];
#pragma unroll
    for (int o = 0; o < 16; o++) acc[o] = 0ull;
    for (int k = 0; k < 64; k++) {
        u64 a2 = pdup(xr[base + k * HW]);
        u64 c2 = pdup(xi[base + k * HW]);
#pragma unroll
        for (int o = 0; o < 16; o++) {
            ulonglong2 m = sM[o * 64 + k];
            acc[o] = ffma2(a2, m.x, acc[o]);
            acc[o] = ffma2(c2, m.y, acc[o]);
        }
    }
#pragma unroll
    for (int o = 0; o < 16; o++) {
        int gi = base + (oc0 + o) * HW;
        float2 v = unpk(acc[o]);
        if (add_resid) { v.x += resr[gi]; v.y += resi[gi]; }
        outr[gi] = v.x; outi[gi] = v.y;
    }
}

// ---------------- evo = exp(lam * dt) ----------------------------------------
__global__ void evo_kernel(const float* __restrict__ dt,
                           const float* __restrict__ lam_re, const float* __restrict__ lam_im,
                           float2* __restrict__ evo)
{
    int i = blockIdx.x * blockDim.x + threadIdx.x;
    if (i >= BB * TT * DD) return;
    int d = i & 63;
    int b = i >> 10, t = (i >> 6) & 15;
    float dtv = dt[b * 16 + t];
    float lre = -log1pf(expf(lam_re[d]));
    float m = expf(lre * dtv);
    float s, c;
    sincosf(lam_im[d] * dtv, &s, &c);
    evo[i] = make_float2(m * c, m * s);
}

// ---------------- diagonal temporal scan over T=16, in place -----------------
__global__ void scan_kernel(float* __restrict__ er, float* __restrict__ ei,
                            const float2* __restrict__ evo)
{
    int idx = blockIdx.x * 256 + threadIdx.x;
    int b = idx >> 18;
    int dhw = idx & 262143;
    int d = dhw >> 12;
    float hr = 0.f, hi = 0.f;
#pragma unroll
    for (int t = 0; t < 16; t++) {
        float2 a = evo[(b * 16 + t) * 64 + d];
        int gi = (b * 16 + t) * (DD * HW) + dhw;
        float xr = er[gi], xv = ei[gi];
        float nr = a.x * hr - a.y * hi + xr;
        float ni = a.x * hi + a.y * hr + xv;
        hr = nr; hi = ni;
        er[gi] = hr; ei[gi] = hi;
    }
}

// ---------------- fused LN + MLP(128->256 gelu ->128) + resid (FFMA2) --------
__global__ void mlp_kernel(const float* __restrict__ x2r, const float* __restrict__ x2i,
                           const float* __restrict__ lnw, const float* __restrict__ lnb,
                           const float* __restrict__ w1,  const float* __restrict__ b1,
                           const float* __restrict__ w2,  const float* __restrict__ b2,
                           float* __restrict__ out)
{
    __shared__ __align__(16) float smem[12288];  // 48 KB
    float* sZ = smem;            // [128 feat][32 pos]
    float* sH = smem + 4096;     // [32 pos][256 hid]
    int tid = threadIdx.x;
    int p0 = blockIdx.x * 32;
    int base = (p0 >> 12) * (DD * HW) + (p0 & 4095);

    for (int i = tid; i < 2048; i += 256) {
        int d = i >> 5, p = i & 31;
        sZ[d * 32 + p]        = x2r[base + d * HW + p];
        sZ[(64 + d) * 32 + p] = x2i[base + d * HW + p];
    }
    __syncthreads();
    {   // LN: 8 threads per position
        int p = tid >> 3, l = tid & 7;
        float sum = 0.f, sq = 0.f;
#pragma unroll
        for (int c = l; c < 128; c += 8) { float v = sZ[c * 32 + p]; sum += v; sq += v * v; }
#pragma unroll
        for (int m = 1; m < 8; m <<= 1) {
            sum += __shfl_xor_sync(0xffffffffu, sum, m);
            sq  += __shfl_xor_sync(0xffffffffu, sq,  m);
        }
        float mu = sum * (1.f / 128.f);
        float rs = rsqrtf(sq * (1.f / 128.f) - mu * mu + 1e-5f);
#pragma unroll
        for (int c = l; c < 128; c += 8) {
            float v = sZ[c * 32 + p];
            sZ[c * 32 + p] = (v - mu) * rs * lnw[c] + lnb[c];
        }
    }
    __syncthreads();
    {   // GEMM1 + gelu: thread = hidden unit j, packed position-pairs
        u64 acc[16];
#pragma unroll
        for (int q = 0; q < 16; q++) acc[q] = 0ull;
        int j = tid;
        for (int k = 0; k < 128; k++) {
            u64 wv2 = pdup(w1[k * 256 + j]);
            const u64* zp = (const u64*)&sZ[k * 32];
#pragma unroll
            for (int q = 0; q < 16; q++)
                acc[q] = ffma2(zp[q], wv2, acc[q]);
        }
        float bb = b1[j];
#pragma unroll
        for (int q = 0; q < 16; q++) {
            float2 v = unpk(acc[q]);
            float h0 = v.x + bb, h1 = v.y + bb;
            h0 = 0.5f * h0 * (1.f + erff(h0 * 0.70710678118654752f));
            h1 = 0.5f * h1 * (1.f + erff(h1 * 0.70710678118654752f));
            sH[(2 * q) * 256 + j]     = h0;
            sH[(2 * q + 1) * 256 + j] = h1;
        }
    }
    __syncthreads();
    int op = tid & 63;            // output pair index 0..63
    int pg = (tid >> 6) * 8;      // position group base
    u64 acc2[8];
    {
#pragma unroll
        for (int q = 0; q < 8; q++) acc2[q] = 0ull;
        const float2* w2p = (const float2*)w2;
        for (int k = 0; k < 256; k++) {
            float2 wp = w2p[k * 64 + op];
            u64 wv = pack2(wp.x, wp.y);
#pragma unroll
            for (int q = 0; q < 8; q++) {
                u64 h2 = pdup(sH[(pg + q) * 256 + k]);
                acc2[q] = ffma2(h2, wv, acc2[q]);
            }
        }
    }
    __syncthreads();
    {
        float bx = b2[2 * op], by = b2[2 * op + 1];
#pragma unroll
        for (int q = 0; q < 8; q++) {
            float2 v = unpk(acc2[q]);
            *(u64*)&smem[(pg + q) * 130 + 2 * op] = pack2(v.x + bx, v.y + by);
        }
    }
    __syncthreads();
    for (int i = tid; i < 4096; i += 256) {
        int c = i >> 5, p = i & 31;
        int dd = c >> 1, comp = c & 1;
        int gi = base + dd * HW + p;
        float v = smem[p * 130 + (comp ? 64 + dd : dd)];
        out[2 * gi + comp] = v + (comp ? x2i[gi] : x2r[gi]);
    }
}

// -----------------------------------------------------------------------------
extern "C" void kernel_launch(void* const* d_in, const int* in_sizes, int n_in,
                              void* d_out, int out_size)
{
    (void)in_sizes; (void)n_in; (void)out_size;
    const float* x_real  = (const float*)d_in[0];
    const float* x_imag  = (const float*)d_in[1];
    const float* dt      = (const float*)d_in[2];
    const float* ln_s_w  = (const float*)d_in[3];
    const float* ln_s_b  = (const float*)d_in[4];
    const float* ln_t_w  = (const float*)d_in[5];
    const float* ln_t_b  = (const float*)d_in[6];
    const float* ln_m_w  = (const float*)d_in[7];
    const float* ln_m_b  = (const float*)d_in[8];
    const float* cw_r    = (const float*)d_in[9];
    const float* cw_i    = (const float*)d_in[10];
    const float* cb_r    = (const float*)d_in[11];
    const float* cb_i    = (const float*)d_in[12];
    const float* spec_wr = (const float*)d_in[13];
    const float* spec_wi = (const float*)d_in[14];
    const float* gate    = (const float*)d_in[15];
    const float* lam_re  = (const float*)d_in[16];
    const float* lam_im  = (const float*)d_in[17];
    const float* V_re    = (const float*)d_in[18];
    const float* V_im    = (const float*)d_in[19];
    const float* Vinv_re = (const float*)d_in[20];
    const float* Vinv_im = (const float*)d_in[21];
    const float* w1      = (const float*)d_in[22];
    const float* b1      = (const float*)d_in[23];
    const float* w2      = (const float*)d_in[24];
    const float* b2      = (const float*)d_in[25];
    float* out = (float*)d_out;

    float *xnr, *xni, *cr, *ci, *x1r, *x1i, *tnr, *tni, *er, *ei, *x2r, *x2i;
    float2* evo;
    cudaGetSymbolAddress((void**)&xnr, g_xnr);
    cudaGetSymbolAddress((void**)&xni, g_xni);
    cudaGetSymbolAddress((void**)&cr,  g_cr);
    cudaGetSymbolAddress((void**)&ci,  g_ci);
    cudaGetSymbolAddress((void**)&x1r, g_x1r);
    cudaGetSymbolAddress((void**)&x1i, g_x1i);
    cudaGetSymbolAddress((void**)&tnr, g_tnr);
    cudaGetSymbolAddress((void**)&tni, g_tni);
    cudaGetSymbolAddress((void**)&er,  g_er);
    cudaGetSymbolAddress((void**)&ei,  g_ei);
    cudaGetSymbolAddress((void**)&x2r, g_x2r);
    cudaGetSymbolAddress((void**)&x2i, g_x2i);
    cudaGetSymbolAddress((void**)&evo, g_evo);

    // ---- spatial stage ----
    cnorm_kernel<<<512, 256>>>(x_real, x_imag, ln_s_w, ln_s_b, xnr, xni);
    conv_kernel<<<dim3(4, 8, 32), dim3(16, 16)>>>(xnr, xni, cw_r, cw_i, cb_r, cb_i, cr, ci);
    spec_kernel<<<2048, 512>>>(xnr, xni, spec_wr, spec_wi, cr, ci,
                               x_real, x_imag, gate, x1r, x1i);
    // ---- temporal stage ----
    cnorm_kernel<<<512, 256>>>(x1r, x1i, ln_t_w, ln_t_b, tnr, tni);
    cproj_kernel<<<dim3(512, 4), 256>>>(tnr, tni, Vinv_re, Vinv_im,
                                        tnr, tni, er, ei, 0);
    evo_kernel<<<8, 256>>>(dt, lam_re, lam_im, evo);
    scan_kernel<<<2048, 256>>>(er, ei, evo);
    cproj_kernel<<<dim3(512, 4), 256>>>(er, ei, V_re, V_im,
                                        x1r, x1i, x2r, x2i, 1);
    // ---- MLP stage -> final interleaved output ----
    mlp_kernel<<<4096, 256>>>(x2r, x2i, ln_m_w, ln_m_b, w1, b1, w2, b2, out);
}